// round 2
// baseline (speedup 1.0000x reference)
#include <cuda_runtime.h>

#define NB  16
#define SEQ 2048
#define DIM 1024

typedef unsigned long long ull;

// ---- scratch (device globals: allocation-free) ----
__device__ float g_sc[(size_t)NB * SEQ * SEQ];   // scores / probs (268 MB)
__device__ float g_x [(size_t)NB * SEQ * DIM];   // X = LN(Q + attnV)
__device__ float g_h [(size_t)NB * SEQ * DIM];   // relu(X W1^T + b1)
__device__ float g_t [(size_t)NB * SEQ * DIM];   // attnV, then ffn out

// ---- packed f32x2 helpers (sm_100+; FFMA2 only reachable via PTX) ----
__device__ __forceinline__ ull pk2(float lo, float hi) {
    ull r;
    asm("mov.b64 %0, {%1, %2};"
        : "=l"(r) : "r"(__float_as_uint(lo)), "r"(__float_as_uint(hi)));
    return r;
}
__device__ __forceinline__ void upk2(ull v, float& lo, float& hi) {
    unsigned ul, uh;
    asm("mov.b64 {%0, %1}, %2;" : "=r"(ul), "=r"(uh) : "l"(v));
    lo = __uint_as_float(ul); hi = __uint_as_float(uh);
}
__device__ __forceinline__ ull ffma2(ull a, ull b, ull c) {
    ull d;
    asm("fma.rn.f32x2 %0, %1, %2, %3;" : "=l"(d) : "l"(a), "l"(b), "l"(c));
    return d;
}

__device__ __forceinline__ float wred_sum(float v) {
#pragma unroll
    for (int o = 16; o > 0; o >>= 1) v += __shfl_xor_sync(0xffffffffu, v, o);
    return v;
}
__device__ __forceinline__ float wred_max(float v) {
#pragma unroll
    for (int o = 16; o > 0; o >>= 1) v = fmaxf(v, __shfl_xor_sync(0xffffffffu, v, o));
    return v;
}

// ============================================================================
// GEMM: C = alpha * A * op(B) (+ bias) (+ relu)
//   A: M x K row-major
//   BT=true : B is N x K row-major  (C = A * B^T)
//   BT=false: B is K x N row-major  (C = A * B)
// Tiles: 128x128x16, 256 threads, 8x8 per-thread microtile via FFMA2 pairs.
// All dims are multiples of tile sizes for this problem.
// ============================================================================
template <bool BT, bool RELU, bool BIAS>
__global__ __launch_bounds__(256, 2)
void gemm_kernel(const float* __restrict__ A, const float* __restrict__ B,
                 float* __restrict__ C, const float* __restrict__ bias,
                 int N, int K, float alpha,
                 size_t sA, size_t sB, size_t sC)
{
    __shared__ float As[16][128];
    __shared__ float Bs[16][128];

    const int zb = blockIdx.z;
    A += (size_t)zb * sA;
    B += (size_t)zb * sB;
    C += (size_t)zb * sC;

    const int tid = threadIdx.x;
    const int tx  = tid & 15;
    const int ty  = tid >> 4;
    const size_t rowBase = (size_t)blockIdx.y * 128;
    const size_t colBase = (size_t)blockIdx.x * 128;

    // loader mappings
    const int lr  = tid >> 2;          // 0..63, row within tile
    const int lc  = (tid & 3) << 2;    // 0,4,8,12 (k offset)
    const int brr = tid >> 5;          // 0..7 (k row for BT=false)
    const int bcc = (tid & 31) << 2;   // 0..124

    // accumulators: 8 rows x 4 column-pairs, packed f32x2
    ull acc2[8][4];
#pragma unroll
    for (int i = 0; i < 8; i++)
#pragma unroll
        for (int j = 0; j < 4; j++) acc2[i][j] = 0ull;  // {0.f, 0.f}

    for (int k0 = 0; k0 < K; k0 += 16) {
#pragma unroll
        for (int s = 0; s < 2; s++) {
            int r = lr + s * 64;
            float4 v = *(const float4*)(A + (rowBase + r) * (size_t)K + k0 + lc);
            As[lc + 0][r] = v.x; As[lc + 1][r] = v.y;
            As[lc + 2][r] = v.z; As[lc + 3][r] = v.w;
        }
        if (BT) {
#pragma unroll
            for (int s = 0; s < 2; s++) {
                int r = lr + s * 64;
                float4 v = *(const float4*)(B + (colBase + r) * (size_t)K + k0 + lc);
                Bs[lc + 0][r] = v.x; Bs[lc + 1][r] = v.y;
                Bs[lc + 2][r] = v.z; Bs[lc + 3][r] = v.w;
            }
        } else {
#pragma unroll
            for (int s = 0; s < 2; s++) {
                int r = brr + s * 8;
                float4 v = *(const float4*)(B + (size_t)(k0 + r) * N + colBase + bcc);
                *(float4*)&Bs[r][bcc] = v;
            }
        }
        __syncthreads();

#pragma unroll
        for (int kk = 0; kk < 16; kk++) {
            float a[8], bb[8];
            *(float4*)&a[0]  = *(const float4*)&As[kk][ty * 8];
            *(float4*)&a[4]  = *(const float4*)&As[kk][ty * 8 + 4];
            *(float4*)&bb[0] = *(const float4*)&Bs[kk][tx * 8];
            *(float4*)&bb[4] = *(const float4*)&Bs[kk][tx * 8 + 4];

            ull a2[8], b2[4];
#pragma unroll
            for (int i = 0; i < 8; i++) a2[i] = pk2(a[i], a[i]);
#pragma unroll
            for (int j = 0; j < 4; j++) b2[j] = pk2(bb[2 * j], bb[2 * j + 1]);

#pragma unroll
            for (int i = 0; i < 8; i++)
#pragma unroll
                for (int j = 0; j < 4; j++)
                    acc2[i][j] = ffma2(a2[i], b2[j], acc2[i][j]);
        }
        __syncthreads();
    }

    float bv[8];
    if (BIAS) {
#pragma unroll
        for (int j = 0; j < 8; j++) bv[j] = bias[colBase + tx * 8 + j];
    }
#pragma unroll
    for (int i = 0; i < 8; i++) {
        float acc[8];
#pragma unroll
        for (int j = 0; j < 4; j++) upk2(acc2[i][j], acc[2 * j], acc[2 * j + 1]);

        float* crow = C + (rowBase + ty * 8 + i) * (size_t)N + colBase + tx * 8;
#pragma unroll
        for (int j = 0; j < 8; j += 4) {
            float4 v;
            v.x = acc[j + 0] * alpha; v.y = acc[j + 1] * alpha;
            v.z = acc[j + 2] * alpha; v.w = acc[j + 3] * alpha;
            if (BIAS) { v.x += bv[j + 0]; v.y += bv[j + 1];
                        v.z += bv[j + 2]; v.w += bv[j + 3]; }
            if (RELU) { v.x = fmaxf(v.x, 0.f); v.y = fmaxf(v.y, 0.f);
                        v.z = fmaxf(v.z, 0.f); v.w = fmaxf(v.w, 0.f); }
            *(float4*)(crow + j) = v;
        }
    }
}

// ============================================================================
// Row softmax over SEQ=2048 elements, one block (256 thr) per row, in place.
// ============================================================================
__global__ __launch_bounds__(256)
void softmax_kernel(float* __restrict__ sc)
{
    const size_t row = blockIdx.x;
    float4* p = reinterpret_cast<float4*>(sc + row * (size_t)SEQ);
    const int t = threadIdx.x;
    __shared__ float red[8];

    float4 v0 = p[t];
    float4 v1 = p[t + 256];

    float m = fmaxf(fmaxf(fmaxf(v0.x, v0.y), fmaxf(v0.z, v0.w)),
                    fmaxf(fmaxf(v1.x, v1.y), fmaxf(v1.z, v1.w)));
    m = wred_max(m);
    if ((t & 31) == 0) red[t >> 5] = m;
    __syncthreads();
    if (t < 32) {
        float x = (t < 8) ? red[t] : -__int_as_float(0x7f800000);
        x = wred_max(x);
        if (t == 0) red[0] = x;
    }
    __syncthreads();
    const float rowmax = red[0];
    __syncthreads();

    v0.x = __expf(v0.x - rowmax); v0.y = __expf(v0.y - rowmax);
    v0.z = __expf(v0.z - rowmax); v0.w = __expf(v0.w - rowmax);
    v1.x = __expf(v1.x - rowmax); v1.y = __expf(v1.y - rowmax);
    v1.z = __expf(v1.z - rowmax); v1.w = __expf(v1.w - rowmax);

    float s = (v0.x + v0.y + v0.z + v0.w) + (v1.x + v1.y + v1.z + v1.w);
    s = wred_sum(s);
    if ((t & 31) == 0) red[t >> 5] = s;
    __syncthreads();
    if (t < 32) {
        float x = (t < 8) ? red[t] : 0.f;
        x = wred_sum(x);
        if (t == 0) red[0] = x;
    }
    __syncthreads();
    const float inv = 1.0f / red[0];

    v0.x *= inv; v0.y *= inv; v0.z *= inv; v0.w *= inv;
    v1.x *= inv; v1.y *= inv; v1.z *= inv; v1.w *= inv;
    p[t] = v0;
    p[t + 256] = v1;
}

// ============================================================================
// out = LayerNorm(A + B) over DIM=1024, one block (256 thr) per row.
// ============================================================================
__global__ __launch_bounds__(256)
void add_ln_kernel(const float* __restrict__ A, const float* __restrict__ Bp,
                   const float* __restrict__ gamma, const float* __restrict__ beta,
                   float* __restrict__ out)
{
    const size_t row = blockIdx.x;
    const float4* a4 = reinterpret_cast<const float4*>(A  + row * (size_t)DIM);
    const float4* b4 = reinterpret_cast<const float4*>(Bp + row * (size_t)DIM);
    float4* o4 = reinterpret_cast<float4*>(out + row * (size_t)DIM);
    const int t = threadIdx.x;
    __shared__ float red[8];

    float4 a = a4[t], b = b4[t];
    float4 x = make_float4(a.x + b.x, a.y + b.y, a.z + b.z, a.w + b.w);

    float s = x.x + x.y + x.z + x.w;
    s = wred_sum(s);
    if ((t & 31) == 0) red[t >> 5] = s;
    __syncthreads();
    if (t < 32) {
        float v = (t < 8) ? red[t] : 0.f;
        v = wred_sum(v);
        if (t == 0) red[0] = v;
    }
    __syncthreads();
    const float mu = red[0] * (1.0f / DIM);
    __syncthreads();

    float4 d = make_float4(x.x - mu, x.y - mu, x.z - mu, x.w - mu);
    float ss = d.x * d.x + d.y * d.y + d.z * d.z + d.w * d.w;
    ss = wred_sum(ss);
    if ((t & 31) == 0) red[t >> 5] = ss;
    __syncthreads();
    if (t < 32) {
        float v = (t < 8) ? red[t] : 0.f;
        v = wred_sum(v);
        if (t == 0) red[0] = v;
    }
    __syncthreads();
    const float var = red[0] * (1.0f / DIM);
    const float r = rsqrtf(var + 1e-5f);

    const float4 g  = reinterpret_cast<const float4*>(gamma)[t];
    const float4 be = reinterpret_cast<const float4*>(beta)[t];
    o4[t] = make_float4(d.x * r * g.x + be.x,
                        d.y * r * g.y + be.y,
                        d.z * r * g.z + be.z,
                        d.w * r * g.w + be.w);
}

// ============================================================================
extern "C" void kernel_launch(void* const* d_in, const int* in_sizes, int n_in,
                              void* d_out, int out_size)
{
    const float* Q     = (const float*)d_in[0];
    const float* K     = (const float*)d_in[1];
    const float* V     = (const float*)d_in[2];
    const float* W1    = (const float*)d_in[3];
    const float* b1    = (const float*)d_in[4];
    const float* W2    = (const float*)d_in[5];
    const float* b2    = (const float*)d_in[6];
    const float* gamma = (const float*)d_in[7];
    const float* beta  = (const float*)d_in[8];
    float* out = (float*)d_out;

    float *sc, *x, *h, *t;
    cudaGetSymbolAddress((void**)&sc, g_sc);
    cudaGetSymbolAddress((void**)&x,  g_x);
    cudaGetSymbolAddress((void**)&h,  g_h);
    cudaGetSymbolAddress((void**)&t,  g_t);

    const float scale = 1.0f / 32.0f;  // 1/(sqrt(1024)+1e-8) in fp32 == 1/32
    dim3 blk(256);

    // 1) scores = scale * Q K^T     (B batched, 2048x2048x1024)
    {
        dim3 g(SEQ / 128, SEQ / 128, NB);
        gemm_kernel<true, false, false><<<g, blk>>>(
            Q, K, sc, nullptr, SEQ, DIM, scale,
            (size_t)SEQ * DIM, (size_t)SEQ * DIM, (size_t)SEQ * SEQ);
    }
    // 2) P = softmax(scores) rowwise, in place
    softmax_kernel<<<NB * SEQ, blk>>>(sc);

    // 3) t = P V                    (B batched, 2048x1024x2048)
    {
        dim3 g(DIM / 128, SEQ / 128, NB);
        gemm_kernel<false, false, false><<<g, blk>>>(
            sc, V, t, nullptr, DIM, SEQ, 1.0f,
            (size_t)SEQ * SEQ, (size_t)SEQ * DIM, (size_t)SEQ * DIM);
    }
    // 4) x = LN(Q + t)
    add_ln_kernel<<<NB * SEQ, blk>>>(Q, t, gamma, beta, x);

    // 5) h = relu(x W1^T + b1)      (32768 x 1024 x 1024)
    {
        dim3 g(DIM / 128, (NB * SEQ) / 128, 1);
        gemm_kernel<true, true, true><<<g, blk>>>(
            x, W1, h, b1, DIM, DIM, 1.0f, 0, 0, 0);
    }
    // 6) t = h W2^T + b2
    {
        dim3 g(DIM / 128, (NB * SEQ) / 128, 1);
        gemm_kernel<true, false, true><<<g, blk>>>(
            h, W2, t, b2, DIM, DIM, 1.0f, 0, 0, 0);
    }
    // 7) out = LN(t + x)
    add_ln_kernel<<<NB * SEQ, blk>>>(t, x, gamma, beta, out);
}

// round 8
// speedup vs baseline: 3.6508x; 3.6508x over previous
#include <cuda_runtime.h>
#include <cuda_bf16.h>
#include <cstdint>

#define NB  16
#define SEQ 2048
#define DIM 1024

typedef unsigned short u16;
typedef unsigned int   u32;
typedef unsigned long long u64;

// ---------------- scratch (device globals: allocation-free) ----------------
__device__ float g_sc[(size_t)NB * SEQ * SEQ];   // fp32 scores
__device__ float g_x [(size_t)NB * SEQ * DIM];   // X residual (fp32)
__device__ float g_t [(size_t)NB * SEQ * DIM];   // attnV / ffn out (fp32)

__device__ u16 g_Qh[(size_t)NB * SEQ * DIM], g_Ql[(size_t)NB * SEQ * DIM];
__device__ u16 g_Kh[(size_t)NB * SEQ * DIM], g_Kl[(size_t)NB * SEQ * DIM];
__device__ u16 g_Vth[(size_t)NB * DIM * SEQ], g_Vtl[(size_t)NB * DIM * SEQ]; // V^T
__device__ u16 g_Ph[(size_t)NB * SEQ * SEQ], g_Pl[(size_t)NB * SEQ * SEQ];
__device__ u16 g_Xh[(size_t)NB * SEQ * DIM], g_Xl[(size_t)NB * SEQ * DIM];
__device__ u16 g_Hh[(size_t)NB * SEQ * DIM], g_Hl[(size_t)NB * SEQ * DIM];
__device__ u16 g_W1h[(size_t)DIM * DIM], g_W1l[(size_t)DIM * DIM];
__device__ u16 g_W2h[(size_t)DIM * DIM], g_W2l[(size_t)DIM * DIM];

// ---------------- small helpers ----------------
__device__ __forceinline__ u32 smem_u32(const void* p) {
    u32 a;
    asm("{ .reg .u64 t; cvta.to.shared.u64 t, %1; cvt.u32.u64 %0, t; }"
        : "=r"(a) : "l"(p));
    return a;
}
__device__ __forceinline__ u16 f2bf(float x) {
    return __bfloat16_as_ushort(__float2bfloat16(x));
}
__device__ __forceinline__ float bf2f(u16 h) {
    return __bfloat162float(__ushort_as_bfloat16(h));
}
__device__ __forceinline__ void split2(float x, u16& h, u16& l) {
    h = f2bf(x);
    l = f2bf(x - bf2f(h));
}

__device__ __forceinline__ float wred_sum(float v) {
#pragma unroll
    for (int o = 16; o > 0; o >>= 1) v += __shfl_xor_sync(0xffffffffu, v, o);
    return v;
}
__device__ __forceinline__ float wred_max(float v) {
#pragma unroll
    for (int o = 16; o > 0; o >>= 1) v = fmaxf(v, __shfl_xor_sync(0xffffffffu, v, o));
    return v;
}

// ---------------- mma.sync / ldmatrix / cp.async (plain sm_103 PTX) --------
__device__ __forceinline__ void ldsm4(u32* d, u32 addr) {
    asm volatile("ldmatrix.sync.aligned.m8n8.x4.shared.b16 {%0,%1,%2,%3}, [%4];"
        : "=r"(d[0]), "=r"(d[1]), "=r"(d[2]), "=r"(d[3]) : "r"(addr));
}
__device__ __forceinline__ void mma16816(float* c, const u32* a, const u32* b) {
    asm volatile(
        "mma.sync.aligned.m16n8k16.row.col.f32.bf16.bf16.f32 "
        "{%0,%1,%2,%3}, {%4,%5,%6,%7}, {%8,%9}, {%0,%1,%2,%3};"
        : "+f"(c[0]), "+f"(c[1]), "+f"(c[2]), "+f"(c[3])
        : "r"(a[0]), "r"(a[1]), "r"(a[2]), "r"(a[3]), "r"(b[0]), "r"(b[1]));
}
__device__ __forceinline__ void cpa16(u32 dst, const void* src) {
    asm volatile("cp.async.cg.shared.global [%0], [%1], 16;"
        :: "r"(dst), "l"(src));
}
#define CP_COMMIT() asm volatile("cp.async.commit_group;" ::: "memory")
#define CP_WAIT0()  asm volatile("cp.async.wait_group 0;"  ::: "memory")

// smem geometry: BM=BN=128, BK=32, row padded to 40 bf16 (80 B, 16B-multiple)
static constexpr int LDS_ROW  = 40;
static constexpr int TILE_B   = 128 * LDS_ROW * 2;           // 10240 B per tile
static constexpr int STAGE_B  = 4 * TILE_B;                  // Ah,Al,Bh,Bl
static constexpr int SMEM_DYN = 2 * STAGE_B;                 // 81920 B

// ============================================================================
// mma.sync GEMM:  C[M,N] = A[M,K] * B[N,K]^T  (bf16 hi/lo split, fp32 accum)
// OM=0: fp32 out; OM=1: bf16-split out. Optional bias/relu fused.
// grid (N/128, M/128, batch), block 256 = 8 warps (warp tile 32x64).
// ============================================================================
template <int OM, bool BIAS, bool RELU>
__global__ void __launch_bounds__(256, 1)
gemm_mma(const u16* __restrict__ Ah, const u16* __restrict__ Al,
         const u16* __restrict__ Bh, const u16* __restrict__ Bl,
         float* __restrict__ C, u16* __restrict__ Ch, u16* __restrict__ Cl,
         const float* __restrict__ bias,
         int Kd, int Nld, size_t sA, size_t sB, size_t sC)
{
    extern __shared__ u16 sm[];
    const int tid  = threadIdx.x;
    const int lane = tid & 31;
    const int wid  = tid >> 5;
    const int wm   = wid >> 1;          // 0..3  -> warp row tile (32 rows)
    const int wn   = wid & 1;           // 0..1  -> warp col tile (64 cols)

    const int z = blockIdx.z;
    Ah += (size_t)z * sA; Al += (size_t)z * sA;
    Bh += (size_t)z * sB; Bl += (size_t)z * sB;
    if (OM == 0) C += (size_t)z * sC;
    else { Ch += (size_t)z * sC; Cl += (size_t)z * sC; }

    const size_t rowBase = (size_t)blockIdx.y * 128;
    const size_t colBase = (size_t)blockIdx.x * 128;
    const u32 smBase = smem_u32(sm);

    float acc[2][8][4];
#pragma unroll
    for (int i = 0; i < 2; i++)
#pragma unroll
        for (int j = 0; j < 8; j++)
#pragma unroll
            for (int k = 0; k < 4; k++) acc[i][j][k] = 0.f;

    const int nC = Kd >> 5;   // K-chunks of 32

    // ---- async chunk loader: 4 tiles x 128 rows x 32 bf16 (16B per op) ----
    auto issue_chunk = [&](int c, int s) {
        const int k0 = c << 5;
        const u32 sb = smBase + (u32)s * STAGE_B;
#pragma unroll
        for (int it = 0; it < 2; it++) {
            int seg = it * 256 + tid;         // 0..511
            int row = seg >> 2, sc = (seg & 3) << 3;
            u32 so = (u32)(row * LDS_ROW + sc) * 2;
            const size_t ga = (rowBase + row) * (size_t)Kd + k0 + sc;
            const size_t gb = (colBase + row) * (size_t)Kd + k0 + sc;
            cpa16(sb + 0 * TILE_B + so, Ah + ga);
            cpa16(sb + 1 * TILE_B + so, Al + ga);
            cpa16(sb + 2 * TILE_B + so, Bh + gb);
            cpa16(sb + 3 * TILE_B + so, Bl + gb);
        }
    };

    // ldmatrix address components (canonical m16n8k16 fragment mappings)
    const int arow = wm * 32 + (lane & 15);
    const int acol = (lane >> 4) << 3;
    const int brow = wn * 64 + (lane & 7) + ((lane >> 4) << 3);
    const int bcol = ((lane >> 3) & 1) << 3;

    auto compute = [&](int s) {
        const u32 sb = smBase + (u32)s * STAGE_B;
        const u32 aH = sb, aL = sb + TILE_B, bH = sb + 2 * TILE_B, bL = sb + 3 * TILE_B;
#pragma unroll
        for (int kk = 0; kk < 32; kk += 16) {
            u32 afh[2][4], afl[2][4], bfh[4][4], bfl[4][4];
#pragma unroll
            for (int fm = 0; fm < 2; fm++) {
                u32 ao = (u32)((arow + fm * 16) * LDS_ROW + kk + acol) * 2;
                ldsm4(afh[fm], aH + ao);
                ldsm4(afl[fm], aL + ao);
            }
#pragma unroll
            for (int fb = 0; fb < 4; fb++) {
                u32 bo = (u32)((brow + fb * 16) * LDS_ROW + kk + bcol) * 2;
                ldsm4(bfh[fb], bH + bo);
                ldsm4(bfl[fb], bL + bo);
            }
#pragma unroll
            for (int fm = 0; fm < 2; fm++)
#pragma unroll
                for (int fn = 0; fn < 8; fn++) {
                    const u32* b2h = &bfh[fn >> 1][(fn & 1) * 2];
                    const u32* b2l = &bfl[fn >> 1][(fn & 1) * 2];
                    mma16816(acc[fm][fn], afh[fm], b2h);   // hi*hi
                    mma16816(acc[fm][fn], afh[fm], b2l);   // hi*lo
                    mma16816(acc[fm][fn], afl[fm], b2h);   // lo*hi
                }
        }
    };

    // ---- 2-stage pipeline ----
    issue_chunk(0, 0);
    CP_COMMIT();
    CP_WAIT0();
    __syncthreads();
    for (int c = 0; c < nC; c++) {
        const int s = c & 1;
        if (c + 1 < nC) { issue_chunk(c + 1, s ^ 1); CP_COMMIT(); }
        compute(s);
        if (c + 1 < nC) CP_WAIT0();
        __syncthreads();
    }

    // ---- epilogue ----
    const int rr = lane >> 2;            // 0..7
    const int cc = (lane & 3) << 1;      // 0,2,4,6
#pragma unroll
    for (int fm = 0; fm < 2; fm++)
#pragma unroll
        for (int fn = 0; fn < 8; fn++) {
            const size_t col = colBase + wn * 64 + fn * 8 + cc;
            float b0 = 0.f, b1 = 0.f;
            if (BIAS) { b0 = __ldg(&bias[col]); b1 = __ldg(&bias[col + 1]); }
#pragma unroll
            for (int hr = 0; hr < 2; hr++) {
                const size_t row = rowBase + wm * 32 + fm * 16 + rr + hr * 8;
                float v0 = acc[fm][fn][hr * 2 + 0] + b0;
                float v1 = acc[fm][fn][hr * 2 + 1] + b1;
                if (RELU) { v0 = fmaxf(v0, 0.f); v1 = fmaxf(v1, 0.f); }
                const size_t off = row * (size_t)Nld + col;
                if (OM == 0) {
                    *(float2*)(C + off) = make_float2(v0, v1);
                } else {
                    u16 h0, l0, h1, l1;
                    split2(v0, h0, l0);
                    split2(v1, h1, l1);
                    *(u32*)(Ch + off) = (u32)h0 | ((u32)h1 << 16);
                    *(u32*)(Cl + off) = (u32)l0 | ((u32)l1 << 16);
                }
            }
        }
}

// ============================================================================
// fp32 -> bf16 hi/lo split (with scale), float4-vectorized
// ============================================================================
__global__ void __launch_bounds__(256)
conv_split(const float* __restrict__ src, u16* __restrict__ hi,
           u16* __restrict__ lo, float scale, size_t n4)
{
    size_t i = (size_t)blockIdx.x * 256 + threadIdx.x;
    if (i >= n4) return;
    float4 v = ((const float4*)src)[i];
    v.x *= scale; v.y *= scale; v.z *= scale; v.w *= scale;
    ushort4 h4, l4;
    split2(v.x, h4.x, l4.x); split2(v.y, h4.y, l4.y);
    split2(v.z, h4.z, l4.z); split2(v.w, h4.w, l4.w);
    ((ushort4*)hi)[i] = h4;
    ((ushort4*)lo)[i] = l4;
}

// ============================================================================
// V[b,s,d] -> Vt hi/lo [b,d,s]  (32x32 smem tiles)
// ============================================================================
__global__ void __launch_bounds__(256)
transpose_split(const float* __restrict__ V, u16* __restrict__ Vth,
                u16* __restrict__ Vtl)
{
    __shared__ float t[32][33];
    const int b = blockIdx.z;
    const int d0 = blockIdx.x * 32, s0 = blockIdx.y * 32;
    const int tx = threadIdx.x & 31, ty = threadIdx.x >> 5;  // 32 x 8
    const float* Vb = V + (size_t)b * SEQ * DIM;
#pragma unroll
    for (int i = 0; i < 4; i++)
        t[ty + i * 8][tx] = Vb[(size_t)(s0 + ty + i * 8) * DIM + d0 + tx];
    __syncthreads();
    u16* oh = Vth + (size_t)b * DIM * SEQ;
    u16* ol = Vtl + (size_t)b * DIM * SEQ;
#pragma unroll
    for (int i = 0; i < 4; i++) {
        float v = t[tx][ty + i * 8];
        u16 h, l; split2(v, h, l);
        size_t o = (size_t)(d0 + ty + i * 8) * SEQ + s0 + tx;
        oh[o] = h; ol[o] = l;
    }
}

// ============================================================================
// Row softmax over SEQ, fp32 in -> bf16 hi/lo out
// ============================================================================
__global__ void __launch_bounds__(256)
softmax_split(const float* __restrict__ sc, u16* __restrict__ Ph,
              u16* __restrict__ Pl)
{
    const size_t row = blockIdx.x;
    const float4* p = (const float4*)(sc + row * (size_t)SEQ);
    const int t = threadIdx.x;
    __shared__ float red[8];

    float4 v0 = p[t];
    float4 v1 = p[t + 256];

    float m = fmaxf(fmaxf(fmaxf(v0.x, v0.y), fmaxf(v0.z, v0.w)),
                    fmaxf(fmaxf(v1.x, v1.y), fmaxf(v1.z, v1.w)));
    m = wred_max(m);
    if ((t & 31) == 0) red[t >> 5] = m;
    __syncthreads();
    if (t < 32) {
        float x = (t < 8) ? red[t] : -__int_as_float(0x7f800000);
        x = wred_max(x);
        if (t == 0) red[0] = x;
    }
    __syncthreads();
    const float rowmax = red[0];
    __syncthreads();

    v0.x = __expf(v0.x - rowmax); v0.y = __expf(v0.y - rowmax);
    v0.z = __expf(v0.z - rowmax); v0.w = __expf(v0.w - rowmax);
    v1.x = __expf(v1.x - rowmax); v1.y = __expf(v1.y - rowmax);
    v1.z = __expf(v1.z - rowmax); v1.w = __expf(v1.w - rowmax);

    float s = (v0.x + v0.y + v0.z + v0.w) + (v1.x + v1.y + v1.z + v1.w);
    s = wred_sum(s);
    if ((t & 31) == 0) red[t >> 5] = s;
    __syncthreads();
    if (t < 32) {
        float x = (t < 8) ? red[t] : 0.f;
        x = wred_sum(x);
        if (t == 0) red[0] = x;
    }
    __syncthreads();
    const float inv = 1.0f / red[0];

    u16* oh = Ph + row * (size_t)SEQ;
    u16* ol = Pl + row * (size_t)SEQ;
    ushort4 h4, l4;
    split2(v0.x * inv, h4.x, l4.x); split2(v0.y * inv, h4.y, l4.y);
    split2(v0.z * inv, h4.z, l4.z); split2(v0.w * inv, h4.w, l4.w);
    ((ushort4*)oh)[t] = h4; ((ushort4*)ol)[t] = l4;
    split2(v1.x * inv, h4.x, l4.x); split2(v1.y * inv, h4.y, l4.y);
    split2(v1.z * inv, h4.z, l4.z); split2(v1.w * inv, h4.w, l4.w);
    ((ushort4*)oh)[t + 256] = h4; ((ushort4*)ol)[t + 256] = l4;
}

// ============================================================================
// out = LayerNorm(A + B); optionally also emit bf16 hi/lo of out
// ============================================================================
template <bool SPLIT>
__global__ void __launch_bounds__(256)
add_ln(const float* __restrict__ A, const float* __restrict__ Bp,
       const float* __restrict__ gamma, const float* __restrict__ beta,
       float* __restrict__ out, u16* __restrict__ oh, u16* __restrict__ ol)
{
    const size_t row = blockIdx.x;
    const float4* a4 = (const float4*)(A  + row * (size_t)DIM);
    const float4* b4 = (const float4*)(Bp + row * (size_t)DIM);
    const int t = threadIdx.x;
    __shared__ float red[8];

    float4 a = a4[t], b = b4[t];
    float4 x = make_float4(a.x + b.x, a.y + b.y, a.z + b.z, a.w + b.w);

    float s = x.x + x.y + x.z + x.w;
    s = wred_sum(s);
    if ((t & 31) == 0) red[t >> 5] = s;
    __syncthreads();
    if (t < 32) {
        float v = (t < 8) ? red[t] : 0.f;
        v = wred_sum(v);
        if (t == 0) red[0] = v;
    }
    __syncthreads();
    const float mu = red[0] * (1.0f / DIM);
    __syncthreads();

    float4 d = make_float4(x.x - mu, x.y - mu, x.z - mu, x.w - mu);
    float ss = d.x * d.x + d.y * d.y + d.z * d.z + d.w * d.w;
    ss = wred_sum(ss);
    if ((t & 31) == 0) red[t >> 5] = ss;
    __syncthreads();
    if (t < 32) {
        float v = (t < 8) ? red[t] : 0.f;
        v = wred_sum(v);
        if (t == 0) red[0] = v;
    }
    __syncthreads();
    const float var = red[0] * (1.0f / DIM);
    const float r = rsqrtf(var + 1e-5f);

    const float4 g  = ((const float4*)gamma)[t];
    const float4 be = ((const float4*)beta)[t];
    float4 o = make_float4(d.x * r * g.x + be.x, d.y * r * g.y + be.y,
                           d.z * r * g.z + be.z, d.w * r * g.w + be.w);
    ((float4*)(out + row * (size_t)DIM))[t] = o;
    if (SPLIT) {
        ushort4 h4, l4;
        split2(o.x, h4.x, l4.x); split2(o.y, h4.y, l4.y);
        split2(o.z, h4.z, l4.z); split2(o.w, h4.w, l4.w);
        ((ushort4*)(oh + row * (size_t)DIM))[t] = h4;
        ((ushort4*)(ol + row * (size_t)DIM))[t] = l4;
    }
}

// ============================================================================
extern "C" void kernel_launch(void* const* d_in, const int* in_sizes, int n_in,
                              void* d_out, int out_size)
{
    const float* Q     = (const float*)d_in[0];
    const float* K     = (const float*)d_in[1];
    const float* V     = (const float*)d_in[2];
    const float* W1    = (const float*)d_in[3];
    const float* b1    = (const float*)d_in[4];
    const float* W2    = (const float*)d_in[5];
    const float* b2    = (const float*)d_in[6];
    const float* gamma = (const float*)d_in[7];
    const float* beta  = (const float*)d_in[8];
    float* out = (float*)d_out;

    float *sc, *x, *t;
    u16 *Qh, *Ql, *Kh, *Kl, *Vth, *Vtl, *Ph, *Pl, *Xh, *Xl, *Hh, *Hl;
    u16 *W1h, *W1l, *W2h, *W2l;
    cudaGetSymbolAddress((void**)&sc, g_sc);
    cudaGetSymbolAddress((void**)&x,  g_x);
    cudaGetSymbolAddress((void**)&t,  g_t);
    cudaGetSymbolAddress((void**)&Qh, g_Qh); cudaGetSymbolAddress((void**)&Ql, g_Ql);
    cudaGetSymbolAddress((void**)&Kh, g_Kh); cudaGetSymbolAddress((void**)&Kl, g_Kl);
    cudaGetSymbolAddress((void**)&Vth, g_Vth); cudaGetSymbolAddress((void**)&Vtl, g_Vtl);
    cudaGetSymbolAddress((void**)&Ph, g_Ph); cudaGetSymbolAddress((void**)&Pl, g_Pl);
    cudaGetSymbolAddress((void**)&Xh, g_Xh); cudaGetSymbolAddress((void**)&Xl, g_Xl);
    cudaGetSymbolAddress((void**)&Hh, g_Hh); cudaGetSymbolAddress((void**)&Hl, g_Hl);
    cudaGetSymbolAddress((void**)&W1h, g_W1h); cudaGetSymbolAddress((void**)&W1l, g_W1l);
    cudaGetSymbolAddress((void**)&W2h, g_W2h); cudaGetSymbolAddress((void**)&W2l, g_W2l);

    cudaFuncSetAttribute(gemm_mma<0, false, false>,
                         cudaFuncAttributeMaxDynamicSharedMemorySize, SMEM_DYN);
    cudaFuncSetAttribute(gemm_mma<1, true, true>,
                         cudaFuncAttributeMaxDynamicSharedMemorySize, SMEM_DYN);
    cudaFuncSetAttribute(gemm_mma<0, true, false>,
                         cudaFuncAttributeMaxDynamicSharedMemorySize, SMEM_DYN);

    const float scale = 1.0f / 32.0f;   // 1/(sqrt(1024)+1e-8) == 1/32 in fp32
    const size_t nQK = (size_t)NB * SEQ * DIM;
    dim3 blk(256);

    // splits: Q (scaled), K; weights; V transpose+split
    conv_split<<<(unsigned)((nQK / 4 + 255) / 256), blk>>>(Q, Qh, Ql, scale, nQK / 4);
    conv_split<<<(unsigned)((nQK / 4 + 255) / 256), blk>>>(K, Kh, Kl, 1.0f, nQK / 4);
    {
        size_t nW = (size_t)DIM * DIM / 4;
        conv_split<<<(unsigned)((nW + 255) / 256), blk>>>(W1, W1h, W1l, 1.0f, nW);
        conv_split<<<(unsigned)((nW + 255) / 256), blk>>>(W2, W2h, W2l, 1.0f, nW);
    }
    transpose_split<<<dim3(DIM / 32, SEQ / 32, NB), blk>>>(V, Vth, Vtl);

    // 1) scores = (Q*scale) K^T  -> fp32
    gemm_mma<0, false, false><<<dim3(SEQ / 128, SEQ / 128, NB), blk, SMEM_DYN>>>(
        Qh, Ql, Kh, Kl, sc, nullptr, nullptr, nullptr,
        DIM, SEQ, (size_t)SEQ * DIM, (size_t)SEQ * DIM, (size_t)SEQ * SEQ);

    // 2) P = softmax(scores) -> bf16 hi/lo
    softmax_split<<<NB * SEQ, blk>>>(sc, Ph, Pl);

    // 3) attnV = P V  (B = V^T, K-major) -> fp32
    gemm_mma<0, false, false><<<dim3(DIM / 128, SEQ / 128, NB), blk, SMEM_DYN>>>(
        Ph, Pl, Vth, Vtl, t, nullptr, nullptr, nullptr,
        SEQ, DIM, (size_t)SEQ * SEQ, (size_t)DIM * SEQ, (size_t)SEQ * DIM);

    // 4) X = LN(Q + attnV) -> fp32 + bf16 hi/lo
    add_ln<true><<<NB * SEQ, blk>>>(Q, t, gamma, beta, x, Xh, Xl);

    // 5) h = relu(X W1^T + b1) -> bf16 hi/lo
    gemm_mma<1, true, true><<<dim3(DIM / 128, (NB * SEQ) / 128, 1), blk, SMEM_DYN>>>(
        Xh, Xl, W1h, W1l, nullptr, Hh, Hl, b1, DIM, DIM, 0, 0, 0);

    // 6) ffn = h W2^T + b2 -> fp32
    gemm_mma<0, true, false><<<dim3(DIM / 128, (NB * SEQ) / 128, 1), blk, SMEM_DYN>>>(
        Hh, Hl, W2h, W2l, t, nullptr, nullptr, b2, DIM, DIM, 0, 0, 0);

    // 7) out = LN(ffn + X)
    add_ln<false><<<NB * SEQ, blk>>>(t, x, gamma, beta, out, nullptr, nullptr);
}